// round 16
// baseline (speedup 1.0000x reference)
#include <cuda_runtime.h>
#include <cuda_fp16.h>
#include <cstdint>

#define B_  32
#define T_  1024
#define S_  1024
#define D_  512
#define K2_ 1024          // 2*D
#define M_  (B_ * T_)     // 32768

// GEMM tiling
#define BM 128
#define BN 256
#define BKc 32            // k per chunk (two m16n8k16 k-steps)
#define NCH (K2_ / BKc)   // 32 chunks
#define NSTAGE 3
#define NTHREADS 512

// smem layout (bytes, per stage): 64B data + 16B pad = 80B row stride
#define A_ROW   80
#define A_OFF   0
#define W_OFF   (128 * A_ROW)             // 10240
#define STAGE_SZ (W_OFF + 256 * A_ROW)    // 30720
#define SMEM_TOTAL (NSTAGE * STAGE_SZ)    // 92160 -> 2 CTAs/SM

// ---------------------------------------------------------------------------
// device scratch (module globals)
// ---------------------------------------------------------------------------
__device__ int d_j[M_];
__device__ __align__(16) __half d_W16[D_ * K2_];

// ---------------------------------------------------------------------------
// PTX helpers
// ---------------------------------------------------------------------------
__device__ __forceinline__ uint32_t smem_u32(const void* p) {
    uint32_t a;
    asm("{ .reg .u64 t; cvta.to.shared.u64 t, %1; cvt.u32.u64 %0, t; }"
        : "=r"(a) : "l"(p));
    return a;
}
__device__ __forceinline__ void cp16(uint32_t dst, const void* src) {
    asm volatile("cp.async.cg.shared.global [%0], [%1], 16;" :: "r"(dst), "l"(src));
}
#define CP_COMMIT() asm volatile("cp.async.commit_group;" ::: "memory")
#define CP_WAIT(n)  asm volatile("cp.async.wait_group %0;" :: "n"(n) : "memory")

__device__ __forceinline__ void ldsm4(uint32_t* r, uint32_t addr) {
    asm volatile("ldmatrix.sync.aligned.m8n8.x4.shared.b16 {%0,%1,%2,%3}, [%4];"
                 : "=r"(r[0]), "=r"(r[1]), "=r"(r[2]), "=r"(r[3]) : "r"(addr));
}
__device__ __forceinline__ void mma16816(float* c, const uint32_t* a,
                                         uint32_t b0, uint32_t b1) {
    asm volatile(
        "mma.sync.aligned.m16n8k16.row.col.f32.f16.f16.f32 "
        "{%0,%1,%2,%3}, {%4,%5,%6,%7}, {%8,%9}, {%0,%1,%2,%3};"
        : "+f"(c[0]), "+f"(c[1]), "+f"(c[2]), "+f"(c[3])
        : "r"(a[0]), "r"(a[1]), "r"(a[2]), "r"(a[3]), "r"(b0), "r"(b1));
}
__device__ __forceinline__ float tanh_fast(float x) {
    float y;
    asm("tanh.approx.f32 %0, %1;" : "=f"(y) : "f"(x));
    return y;
}

// ---------------------------------------------------------------------------
// 1) merged: compute_j (blocks 0..31) + prep_w (blocks 32..543)
// ---------------------------------------------------------------------------
__global__ void prep_misc_kernel(const int* __restrict__ w32,
                                 const float* __restrict__ W) {
    const int bid = blockIdx.x;
    const int t = threadIdx.x;
    if (bid < B_) {
        // --- j indices (token buffer int32 or int64, detected on device)
        __shared__ int s[T_];
        __shared__ int is64_s;
        if (t == 0) {
            int allzero = 1;
            #pragma unroll
            for (int i = 1; i < 64; i += 2) allzero &= (w32[i] == 0);
            is64_s = allzero;
        }
        __syncthreads();
        const int idx = bid * T_ + t;
        const int tok = is64_s ? w32[idx * 2] : w32[idx];
        int flag = (t >= 1 && (tok == 1 || tok == 2)) ? 1 : 0;
        s[t] = flag;
        __syncthreads();
        #pragma unroll
        for (int off = 1; off < T_; off <<= 1) {
            int v = (t >= off) ? s[t - off] : 0;
            __syncthreads();
            s[t] += v;
            __syncthreads();
        }
        int jj;
        if (t == 0) jj = 0;
        else { jj = t - s[t] - 1; if (jj < 0) jj += S_; }
        d_j[idx] = jj;
    } else {
        // --- W -> fp16
        const int n = bid - B_;
        const size_t base = (size_t)n * K2_ + t;
        d_W16[base] = __float2half_rn(W[base]);
    }
}

// ---------------------------------------------------------------------------
// 2) HMMA GEMM (single-pass fp16, fp32 accum), A gathered+converted in-kernel,
//    attn one-hot writes spread over both x-CTAs:
//    out[m,n] = tanh(bias[n] + sum_k A[m,k]*W[n,k])
//    A[m,0:512]=context[b,j[m]], A[m,512:1024]=output[m] (fp32 -> fp16 on load)
//    CTA 128x256, 16 warps 64x32, K-chunk 32, 3-stage pipeline, 1 sync/chunk,
//    2 CTAs/SM. B double-buffered.
// ---------------------------------------------------------------------------
__global__ __launch_bounds__(NTHREADS, 2)
void gemm_mma_kernel(const float* __restrict__ bias, float* __restrict__ out,
                     float* __restrict__ attn,
                     const float* __restrict__ outp,     // [M, D]
                     const float* __restrict__ context)  // [B, S, D]
{
    extern __shared__ char smem[];
    const uint32_t smb = smem_u32(smem);
    const int tid = threadIdx.x;
    const int wid = tid >> 5;
    const int lane = tid & 31;
    const int wm = wid & 1;           // warp m (2): 64 rows
    const int wn = wid >> 1;          // warp n (8): 32 cols
    const int m0 = blockIdx.y * BM;
    const int n0 = blockIdx.x * BN;

    float acc[4][4][4];
    #pragma unroll
    for (int i = 0; i < 4; i++)
        #pragma unroll
        for (int j = 0; j < 4; j++)
            #pragma unroll
            for (int k = 0; k < 4; k++) acc[i][j][k] = 0.f;

    // ---- A loader role: 4 threads per row; 8 fp32 each per chunk
    const int ar = tid >> 2;          // A row 0..127
    const int aq = tid & 3;           // k-quarter (8 floats, 32B)
    const int am = m0 + ar;
    const float* arow_c = context + ((size_t)((am >> 10) << 10) + d_j[am]) * D_;
    const float* arow_o = outp + (size_t)am * D_;
    const uint32_t a_sts = (uint32_t)(A_OFF + ar * A_ROW + aq * 16);

    float4 pf[2];                     // prefetched fp32 A (8 floats)
    auto ldg_a = [&](int c) {
        const int k0 = c * BKc + aq * 8;
        const float* src = (k0 < D_) ? (arow_c + k0) : (arow_o + (k0 - D_));
        pf[0] = ((const float4*)src)[0];
        pf[1] = ((const float4*)src)[1];
    };
    auto sts_a = [&](int s) {
        union { __half2 h2[4]; uint4 u; } pk;
        pk.h2[0] = __floats2half2_rn(pf[0].x, pf[0].y);
        pk.h2[1] = __floats2half2_rn(pf[0].z, pf[0].w);
        pk.h2[2] = __floats2half2_rn(pf[1].x, pf[1].y);
        pk.h2[3] = __floats2half2_rn(pf[1].z, pf[1].w);
        *(uint4*)(smem + s * STAGE_SZ + a_sts) = pk.u;
    };
    // ---- W loader role: 2 threads per row, cp.async
    const int wr = tid >> 1;          // W row 0..255
    const int wh = tid & 1;           // k-half (16 halfs, 32B)
    auto issue_w = [&](int c, int s) {
        const int k0 = c * BKc + wh * 16;
        const __half* src = d_W16 + (size_t)(n0 + wr) * K2_ + k0;
        const uint32_t dst = smb + s * STAGE_SZ + W_OFF + wr * A_ROW + wh * 32;
        cp16(dst, src);
        cp16(dst + 16, src + 8);
    };

    // prologue: stages 0..1 (one stage of write slack)
    #pragma unroll
    for (int s = 0; s < NSTAGE - 1; s++) {
        ldg_a(s); sts_a(s); issue_w(s, s); CP_COMMIT();
    }
    ldg_a(NSTAGE - 1);                // next chunk into regs

    // ldmatrix lane addressing
    const uint32_t aoff = (uint32_t)((wm * 64 + (lane & 15)) * A_ROW + (lane >> 4) * 16);
    const int g = lane >> 3;
    const uint32_t boff = (uint32_t)((wn * 32 + ((g >> 1) << 3) + (lane & 7)) * A_ROW
                                     + (g & 1) * 16);

    // attn split: this CTA covers one-hot cols [x*512, x*512+512)
    const int acb = blockIdx.x * 128;      // float4-unit col base

    int stage = 0;
    int wstage = NSTAGE - 1;
    for (int c = 0; c < NCH; c++) {
        CP_WAIT(1);
        __syncthreads();
        // refill stage consumed at iter c-1: A from regs, W via cp.async
        if (c + NSTAGE - 1 < NCH) {
            sts_a(wstage);
            issue_w(c + NSTAGE - 1, wstage);
        }
        CP_COMMIT();
        if (c + NSTAGE < NCH) ldg_a(c + NSTAGE);   // prefetch next chunk's A

        // attn writes: 4 rows/chunk, this CTA's 512-col half (8KB/chunk)
        {
            const int row = m0 + (c << 2) + (tid >> 7);
            const int j = d_j[row];
            const int cb = acb + (tid & 127);
            float4 v = make_float4(0.f, 0.f, 0.f, 0.f);
            if ((j >> 2) == cb) ((float*)&v)[j & 3] = 1.0f;
            ((float4*)(attn + (size_t)row * S_))[cb] = v;
        }

        const uint32_t st = smb + stage * STAGE_SZ;
        #pragma unroll
        for (int ks = 0; ks < 2; ks++) {
            const uint32_t kb = ks * 32;
            uint32_t a[4][4];
            #pragma unroll
            for (int mt = 0; mt < 4; mt++)
                ldsm4(a[mt], st + A_OFF + aoff + kb + mt * 16 * A_ROW);
            uint32_t bcur[4], bnxt[4];
            ldsm4(bcur, st + W_OFF + boff + kb);
            #pragma unroll
            for (int np = 0; np < 2; np++) {
                if (np + 1 < 2)
                    ldsm4(bnxt, st + W_OFF + boff + kb + (np + 1) * 16 * A_ROW);
                #pragma unroll
                for (int mt = 0; mt < 4; mt++) {
                    mma16816(acc[mt][np * 2],     a[mt], bcur[0], bcur[1]);
                    mma16816(acc[mt][np * 2 + 1], a[mt], bcur[2], bcur[3]);
                }
                #pragma unroll
                for (int q = 0; q < 4; q++) bcur[q] = bnxt[q];
            }
        }

        stage  = (stage  + 1 == NSTAGE) ? 0 : stage + 1;
        wstage = (wstage + 1 == NSTAGE) ? 0 : wstage + 1;
    }

    // ---- epilogue: bias + tanh.approx, float2 stores
    const int r4 = lane >> 2;
    const int c2 = (lane & 3) * 2;
    #pragma unroll
    for (int mt = 0; mt < 4; mt++) {
        #pragma unroll
        for (int nt = 0; nt < 4; nt++) {
            const int gm = m0 + wm * 64 + mt * 16 + r4;
            const int gn = n0 + wn * 32 + nt * 8 + c2;
            const float b0 = bias[gn], b1 = bias[gn + 1];
            float2 v0, v1;
            v0.x = tanh_fast(acc[mt][nt][0] + b0);
            v0.y = tanh_fast(acc[mt][nt][1] + b1);
            v1.x = tanh_fast(acc[mt][nt][2] + b0);
            v1.y = tanh_fast(acc[mt][nt][3] + b1);
            *(float2*)(out + (size_t)gm * D_ + gn) = v0;
            *(float2*)(out + (size_t)(gm + 8) * D_ + gn) = v1;
        }
    }
}

// ---------------------------------------------------------------------------
extern "C" void kernel_launch(void* const* d_in, const int* in_sizes, int n_in,
                              void* d_out, int out_size) {
    const int* input_var = nullptr;
    const float* output  = nullptr;
    const float* context = nullptr;
    const float* W    = nullptr;
    const float* bias = nullptr;

    for (int i = 0; i < n_in; i++) {
        const int sz = in_sizes[i];
        if (sz == B_ * T_) input_var = (const int*)d_in[i];
        else if (sz == B_ * T_ * D_) {
            if (!output) output = (const float*)d_in[i];
            else if (!context) context = (const float*)d_in[i];
        } else if (sz == D_ * K2_) W = (const float*)d_in[i];
        else if (sz == D_) bias = (const float*)d_in[i];
    }

    float* out  = (float*)d_out;                 // [B,T,D]
    float* attn = out + (size_t)M_ * D_;         // [B,T,S]

    static bool attr_set = false;
    if (!attr_set) {
        cudaFuncSetAttribute(gemm_mma_kernel,
                             cudaFuncAttributeMaxDynamicSharedMemorySize, SMEM_TOTAL);
        attr_set = true;
    }

    prep_misc_kernel<<<B_ + D_, 1024>>>(input_var, W);
    dim3 grid(D_ / BN, M_ / BM);  // (2, 256)
    gemm_mma_kernel<<<grid, NTHREADS, SMEM_TOTAL>>>(bias, out, attn, output, context);
}

// round 17
// speedup vs baseline: 2.7650x; 2.7650x over previous
#include <cuda_runtime.h>
#include <cuda_fp16.h>
#include <cstdint>

#define B_  32
#define T_  1024
#define S_  1024
#define D_  512
#define K2_ 1024          // 2*D
#define M_  (B_ * T_)     // 32768

// GEMM tiling (R15-best config)
#define BM 128
#define BN 128
#define BKc 32            // k per chunk (two m16n8k16 k-steps)
#define NCH (K2_ / BKc)   // 32 chunks
#define NSTAGE 5
#define NTHREADS 256

// smem layout (bytes, per stage): 64B data + 16B pad = 80B row stride
#define A_ROW   80
#define A_OFF   0
#define W_OFF   (128 * A_ROW)             // 10240
#define STAGE_SZ (W_OFF + 128 * A_ROW)    // 20480
#define SMEM_TOTAL (NSTAGE * STAGE_SZ)    // 102400 -> 2 CTAs/SM

// ---------------------------------------------------------------------------
// device scratch (module globals)
// ---------------------------------------------------------------------------
__device__ int d_j[M_];
__device__ __align__(16) __half d_W16[D_ * K2_];

// ---------------------------------------------------------------------------
// PTX helpers
// ---------------------------------------------------------------------------
__device__ __forceinline__ uint32_t smem_u32(const void* p) {
    uint32_t a;
    asm("{ .reg .u64 t; cvta.to.shared.u64 t, %1; cvt.u32.u64 %0, t; }"
        : "=r"(a) : "l"(p));
    return a;
}
__device__ __forceinline__ void cp16(uint32_t dst, const void* src) {
    asm volatile("cp.async.cg.shared.global [%0], [%1], 16;" :: "r"(dst), "l"(src));
}
#define CP_COMMIT() asm volatile("cp.async.commit_group;" ::: "memory")
#define CP_WAIT(n)  asm volatile("cp.async.wait_group %0;" :: "n"(n) : "memory")

__device__ __forceinline__ void ldsm4(uint32_t* r, uint32_t addr) {
    asm volatile("ldmatrix.sync.aligned.m8n8.x4.shared.b16 {%0,%1,%2,%3}, [%4];"
                 : "=r"(r[0]), "=r"(r[1]), "=r"(r[2]), "=r"(r[3]) : "r"(addr));
}
__device__ __forceinline__ void mma16816(float* c, const uint32_t* a,
                                         uint32_t b0, uint32_t b1) {
    asm volatile(
        "mma.sync.aligned.m16n8k16.row.col.f32.f16.f16.f32 "
        "{%0,%1,%2,%3}, {%4,%5,%6,%7}, {%8,%9}, {%0,%1,%2,%3};"
        : "+f"(c[0]), "+f"(c[1]), "+f"(c[2]), "+f"(c[3])
        : "r"(a[0]), "r"(a[1]), "r"(a[2]), "r"(a[3]), "r"(b0), "r"(b1));
}
__device__ __forceinline__ float tanh_fast(float x) {
    float y;
    asm("tanh.approx.f32 %0, %1;" : "=f"(y) : "f"(x));
    return y;
}

// ---------------------------------------------------------------------------
// 1) merged: compute_j (blocks 0..31) + prep_w (blocks 32..543)
// ---------------------------------------------------------------------------
__global__ void prep_misc_kernel(const int* __restrict__ w32,
                                 const float* __restrict__ W) {
    const int bid = blockIdx.x;
    const int t = threadIdx.x;
    if (bid < B_) {
        // --- j indices (token buffer int32 or int64, detected on device)
        __shared__ int s[T_];
        __shared__ int is64_s;
        if (t == 0) {
            int allzero = 1;
            #pragma unroll
            for (int i = 1; i < 64; i += 2) allzero &= (w32[i] == 0);
            is64_s = allzero;
        }
        __syncthreads();
        const int idx = bid * T_ + t;
        const int tok = is64_s ? w32[idx * 2] : w32[idx];
        int flag = (t >= 1 && (tok == 1 || tok == 2)) ? 1 : 0;
        s[t] = flag;
        __syncthreads();
        #pragma unroll
        for (int off = 1; off < T_; off <<= 1) {
            int v = (t >= off) ? s[t - off] : 0;
            __syncthreads();
            s[t] += v;
            __syncthreads();
        }
        int jj;
        if (t == 0) jj = 0;
        else { jj = t - s[t] - 1; if (jj < 0) jj += S_; }
        d_j[idx] = jj;
    } else {
        // --- W -> fp16
        const int n = bid - B_;
        const size_t base = (size_t)n * K2_ + t;
        d_W16[base] = __float2half_rn(W[base]);
    }
}

// ---------------------------------------------------------------------------
// 2) HMMA GEMM (single-pass fp16, fp32 accum), A gathered+converted in-kernel,
//    attn one-hot writes balanced across the 4 x-CTAs:
//    out[m,n] = tanh(bias[n] + sum_k A[m,k]*W[n,k])
//    A[m,0:512]=context[b,j[m]], A[m,512:1024]=output[m] (fp32 -> fp16 on load)
//    CTA 128x128, 8 warps 64x32, K-chunk 32, 5-stage pipeline, 1 sync/chunk,
//    2 CTAs/SM. B double-buffered.
// ---------------------------------------------------------------------------
__global__ __launch_bounds__(NTHREADS, 2)
void gemm_mma_kernel(const float* __restrict__ bias, float* __restrict__ out,
                     float* __restrict__ attn,
                     const float* __restrict__ outp,     // [M, D]
                     const float* __restrict__ context)  // [B, S, D]
{
    extern __shared__ char smem[];
    const uint32_t smb = smem_u32(smem);
    const int tid = threadIdx.x;
    const int wid = tid >> 5;
    const int lane = tid & 31;
    const int wm = wid & 1;           // warp m (2): 64 rows
    const int wn = wid >> 1;          // warp n (4): 32 cols
    const int m0 = blockIdx.y * BM;
    const int n0 = blockIdx.x * BN;

    float acc[4][4][4];
    #pragma unroll
    for (int i = 0; i < 4; i++)
        #pragma unroll
        for (int j = 0; j < 4; j++)
            #pragma unroll
            for (int k = 0; k < 4; k++) acc[i][j][k] = 0.f;

    // ---- A loader role: 2 threads per row; 16 fp32 each per chunk
    const int ar = tid >> 1;          // A row 0..127
    const int ah = tid & 1;           // k-half (16 floats)
    const int am = m0 + ar;
    const float* arow_c = context + ((size_t)((am >> 10) << 10) + d_j[am]) * D_;
    const float* arow_o = outp + (size_t)am * D_;
    const uint32_t a_sts = (uint32_t)(A_OFF + ar * A_ROW + ah * 32);

    float4 pf[4];                     // prefetched fp32 A (16 floats)
    auto ldg_a = [&](int c) {
        const int k0 = c * BKc + ah * 16;
        const float* src = (k0 < D_) ? (arow_c + k0) : (arow_o + (k0 - D_));
        pf[0] = ((const float4*)src)[0];
        pf[1] = ((const float4*)src)[1];
        pf[2] = ((const float4*)src)[2];
        pf[3] = ((const float4*)src)[3];
    };
    auto sts_a = [&](int s) {
        union { __half2 h2[8]; uint4 u[2]; } pk;
        #pragma unroll
        for (int i = 0; i < 4; i++) {
            pk.h2[i * 2]     = __floats2half2_rn(pf[i].x, pf[i].y);
            pk.h2[i * 2 + 1] = __floats2half2_rn(pf[i].z, pf[i].w);
        }
        uint4* dst = (uint4*)(smem + s * STAGE_SZ + a_sts);
        dst[0] = pk.u[0];
        dst[1] = pk.u[1];
    };
    // ---- W loader role: 2 threads per row, cp.async
    auto issue_w = [&](int c, int s) {
        const int k0 = c * BKc + ah * 16;
        const __half* src = d_W16 + (size_t)(n0 + ar) * K2_ + k0;
        const uint32_t dst = smb + s * STAGE_SZ + W_OFF + ar * A_ROW + ah * 32;
        cp16(dst, src);
        cp16(dst + 16, src + 8);
    };

    // prologue: stages 0..3 (LDG->STS stall only at startup)
    #pragma unroll
    for (int s = 0; s < NSTAGE - 1; s++) {
        ldg_a(s); sts_a(s); issue_w(s, s); CP_COMMIT();
    }
    ldg_a(NSTAGE - 1);                // chunk 4 into regs

    // ldmatrix lane addressing
    const uint32_t aoff = (uint32_t)((wm * 64 + (lane & 15)) * A_ROW + (lane >> 4) * 16);
    const int g = lane >> 3;
    const uint32_t boff = (uint32_t)((wn * 32 + ((g >> 1) << 3) + (lane & 7)) * A_ROW
                                     + (g & 1) * 16);

    // attn split: this CTA covers one-hot float4-cols [x*64, x*64+64)
    const int acb = blockIdx.x * 64;

    int stage = 0;
    int wstage = NSTAGE - 1;
    for (int c = 0; c < NCH; c++) {
        CP_WAIT(3);
        __syncthreads();
        // refill stage consumed at iter c-1: A from regs, W via cp.async
        if (c + NSTAGE - 1 < NCH) {
            sts_a(wstage);
            issue_w(c + NSTAGE - 1, wstage);
        }
        CP_COMMIT();
        if (c + NSTAGE < NCH) ldg_a(c + NSTAGE);   // prefetch next chunk's A

        // attn writes: 4 rows/chunk, this CTA's 256-col slice (4KB/chunk)
        {
            const int row = m0 + (c << 2) + (tid >> 6);
            const int j = d_j[row];
            const int cb = acb + (tid & 63);
            float4 v = make_float4(0.f, 0.f, 0.f, 0.f);
            if ((j >> 2) == cb) ((float*)&v)[j & 3] = 1.0f;
            ((float4*)(attn + (size_t)row * S_))[cb] = v;
        }

        const uint32_t st = smb + stage * STAGE_SZ;
        #pragma unroll
        for (int ks = 0; ks < 2; ks++) {
            const uint32_t kb = ks * 32;
            uint32_t a[4][4];
            #pragma unroll
            for (int mt = 0; mt < 4; mt++)
                ldsm4(a[mt], st + A_OFF + aoff + kb + mt * 16 * A_ROW);
            uint32_t bcur[4], bnxt[4];
            ldsm4(bcur, st + W_OFF + boff + kb);
            #pragma unroll
            for (int np = 0; np < 2; np++) {
                if (np + 1 < 2)
                    ldsm4(bnxt, st + W_OFF + boff + kb + (np + 1) * 16 * A_ROW);
                #pragma unroll
                for (int mt = 0; mt < 4; mt++) {
                    mma16816(acc[mt][np * 2],     a[mt], bcur[0], bcur[1]);
                    mma16816(acc[mt][np * 2 + 1], a[mt], bcur[2], bcur[3]);
                }
                #pragma unroll
                for (int q = 0; q < 4; q++) bcur[q] = bnxt[q];
            }
        }

        stage  = (stage  + 1 == NSTAGE) ? 0 : stage + 1;
        wstage = (wstage + 1 == NSTAGE) ? 0 : wstage + 1;
    }

    // ---- epilogue: bias + tanh.approx, float2 stores
    const int r4 = lane >> 2;
    const int c2 = (lane & 3) * 2;
    #pragma unroll
    for (int mt = 0; mt < 4; mt++) {
        #pragma unroll
        for (int nt = 0; nt < 4; nt++) {
            const int gm = m0 + wm * 64 + mt * 16 + r4;
            const int gn = n0 + wn * 32 + nt * 8 + c2;
            const float b0 = bias[gn], b1 = bias[gn + 1];
            float2 v0, v1;
            v0.x = tanh_fast(acc[mt][nt][0] + b0);
            v0.y = tanh_fast(acc[mt][nt][1] + b1);
            v1.x = tanh_fast(acc[mt][nt][2] + b0);
            v1.y = tanh_fast(acc[mt][nt][3] + b1);
            *(float2*)(out + (size_t)gm * D_ + gn) = v0;
            *(float2*)(out + (size_t)(gm + 8) * D_ + gn) = v1;
        }
    }
}

// ---------------------------------------------------------------------------
extern "C" void kernel_launch(void* const* d_in, const int* in_sizes, int n_in,
                              void* d_out, int out_size) {
    const int* input_var = nullptr;
    const float* output  = nullptr;
    const float* context = nullptr;
    const float* W    = nullptr;
    const float* bias = nullptr;

    for (int i = 0; i < n_in; i++) {
        const int sz = in_sizes[i];
        if (sz == B_ * T_) input_var = (const int*)d_in[i];
        else if (sz == B_ * T_ * D_) {
            if (!output) output = (const float*)d_in[i];
            else if (!context) context = (const float*)d_in[i];
        } else if (sz == D_ * K2_) W = (const float*)d_in[i];
        else if (sz == D_) bias = (const float*)d_in[i];
    }

    float* out  = (float*)d_out;                 // [B,T,D]
    float* attn = out + (size_t)M_ * D_;         // [B,T,S]

    static bool attr_set = false;
    if (!attr_set) {
        cudaFuncSetAttribute(gemm_mma_kernel,
                             cudaFuncAttributeMaxDynamicSharedMemorySize, SMEM_TOTAL);
        attr_set = true;
    }

    prep_misc_kernel<<<B_ + D_, 1024>>>(input_var, W);
    dim3 grid(D_ / BN, M_ / BM);  // (4, 256)
    gemm_mma_kernel<<<grid, NTHREADS, SMEM_TOTAL>>>(bias, out, attn, output, context);
}